// round 15
// baseline (speedup 1.0000x reference)
#include <cuda_runtime.h>
#include <cuda_fp16.h>
#include <math.h>
#include <stdint.h>

// Problem constants
#define Bc   16
#define L1c  816
#define L2c  51
#define Nc   867
#define Hc   8
#define DHc  256
#define D1c  2048
#define D2c  1024
#define HDc  2048

// ---------------- Scratch (half precision pipeline) ----------------
__device__ __half g_h1h[(size_t)Bc * L1c * D1c];
__device__ __half g_h2h[(size_t)Bc * L2c * D2c];
__device__ __half g_qh [(size_t)Bc * Nc  * HDc];
__device__ __half g_kh [(size_t)Bc * Nc  * HDc];
__device__ __half g_vh [(size_t)Bc * Nc  * HDc];
__device__ __half g_aoh[(size_t)Bc * Nc  * HDc];
__device__ __half g_wth[(size_t)6144*2048 + 6144*1024 + 2048*2048 + 1024*2048];

__device__ __forceinline__ uint32_t smem_u32(const void* p) {
    uint32_t a;
    asm("{ .reg .u64 t; cvta.to.shared.u64 t, %1; cvt.u32.u64 %0, t; }" : "=r"(a) : "l"(p));
    return a;
}
__device__ __forceinline__ void cp16(uint32_t dst, const void* src, bool pred) {
    int sz = pred ? 16 : 0;
    asm volatile("cp.async.cg.shared.global [%0], [%1], 16, %2;"
                 :: "r"(dst), "l"(src), "r"(sz) : "memory");
}
__device__ __forceinline__ void cp_commit() {
    asm volatile("cp.async.commit_group;" ::: "memory");
}
__device__ __forceinline__ void ldm4(unsigned* a, uint32_t addr) {
    asm volatile("ldmatrix.sync.aligned.m8n8.x4.shared.b16 {%0,%1,%2,%3}, [%4];"
                 : "=r"(a[0]), "=r"(a[1]), "=r"(a[2]), "=r"(a[3]) : "r"(addr));
}
__device__ __forceinline__ void ldm4t(unsigned* a, uint32_t addr) {
    asm volatile("ldmatrix.sync.aligned.m8n8.x4.trans.shared.b16 {%0,%1,%2,%3}, [%4];"
                 : "=r"(a[0]), "=r"(a[1]), "=r"(a[2]), "=r"(a[3]) : "r"(addr));
}
#define HMMA(acc, a0,a1,a2,a3, b0,b1) \
    asm volatile( \
        "mma.sync.aligned.m16n8k16.row.col.f32.f16.f16.f32 " \
        "{%0,%1,%2,%3}, {%4,%5,%6,%7}, {%8,%9}, {%0,%1,%2,%3};" \
        : "+f"((acc)[0]), "+f"((acc)[1]), "+f"((acc)[2]), "+f"((acc)[3]) \
        : "r"(a0), "r"(a1), "r"(a2), "r"(a3), "r"(b0), "r"(b1))

__device__ __forceinline__ unsigned h2u(float lo, float hi) {
    __half2 h = __floats2half2_rn(lo, hi);
    return *(unsigned*)&h;
}

// ---------------- Round + transpose to half: out[n][k] = h(in[k][n]) ----------------
__global__ void transround_kernel(const float* __restrict__ in, __half* __restrict__ out,
                                  int K, int N) {
    __shared__ float tile[32][33];
    int nb = blockIdx.x * 32, kb = blockIdx.y * 32;
    int tx = threadIdx.x, ty = threadIdx.y;
    #pragma unroll
    for (int j = 0; j < 4; j++)
        tile[ty + j * 8][tx] = in[(size_t)(kb + ty + j * 8) * N + nb + tx];
    __syncthreads();
    #pragma unroll
    for (int j = 0; j < 4; j++)
        out[(size_t)(nb + ty + j * 8) * K + kb + tx] = __float2half_rn(tile[tx][ty + j * 8]);
}

__global__ void qkv_transround_kernel(const float* __restrict__ wq,
                                      const float* __restrict__ wk,
                                      const float* __restrict__ wv,
                                      __half* __restrict__ out, int K, int N) {
    __shared__ float tile[32][33];
    const float* in = (blockIdx.z == 0) ? wq : ((blockIdx.z == 1) ? wk : wv);
    __half* dst = out + (size_t)blockIdx.z * N * K;
    int nb = blockIdx.x * 32, kb = blockIdx.y * 32;
    int tx = threadIdx.x, ty = threadIdx.y;
    #pragma unroll
    for (int j = 0; j < 4; j++)
        tile[ty + j * 8][tx] = in[(size_t)(kb + ty + j * 8) * N + nb + tx];
    __syncthreads();
    #pragma unroll
    for (int j = 0; j < 4; j++)
        dst[(size_t)(nb + ty + j * 8) * K + kb + tx] = __float2half_rn(tile[tx][ty + j * 8]);
}

// ---------------- RMSNorm (writes half) ----------------
__global__ void rmsnorm_kernel(const float* __restrict__ x, const float* __restrict__ w,
                               __half* __restrict__ out, int D) {
    int row = blockIdx.x;
    const float* xr = x + (size_t)row * D;
    __half* orow = out + (size_t)row * D;
    float ss = 0.f;
    for (int d = threadIdx.x; d < D; d += blockDim.x) {
        float v = xr[d];
        ss += v * v;
    }
    __shared__ float red[256];
    red[threadIdx.x] = ss;
    __syncthreads();
    for (int s = 128; s > 0; s >>= 1) {
        if (threadIdx.x < s) red[threadIdx.x] += red[threadIdx.x + s];
        __syncthreads();
    }
    float scale = rsqrtf(red[0] / (float)D + 1e-6f);
    for (int d = threadIdx.x; d < D; d += blockDim.x)
        orow[d] = __float2half_rn(xr[d] * scale * (1.0f + w[d]));
}

// ---------------- FP16 GEMM (identical to R14) ----------------
#define GBK 64
#define PH  72
#define A_STGH (128 * PH)
#define STG_H  (2 * A_STGH)
#define G_SMEM (3 * STG_H * 2)

__global__ __launch_bounds__(256, 2) void hgemm_kernel(
    const __half* __restrict__ A, int lda,
    const __half* __restrict__ Bt, int ldb,
    void* C0v, void* C1v, void* C2v, int ldc,
    int M, int K,
    int a_seg, int a_outer, int a_off,
    int c_seg, int c_outer, int c_off,
    int blocks_per_out, int half_out)
{
    extern __shared__ __half smh[];
    const int tid  = threadIdx.x;
    const int lane = tid & 31;
    const int warp = tid >> 5;
    const int wm   = warp >> 1;
    const int wn   = warp & 1;
    const int gg   = lane >> 2;
    const int t    = lane & 3;

    const int out = blockIdx.x / blocks_per_out;
    void* Cv = (out == 0) ? C0v : ((out == 1) ? C1v : C2v);
    const int colC = (blockIdx.x % blocks_per_out) * 128;
    const int rowBase = blockIdx.y * 128;
    const int niter = K / GBK;

    const int kc = (tid & 7) * 8;
    long aoffs[4];
    bool aval[4];
    #pragma unroll
    for (int j = 0; j < 4; j++) {
        int r = rowBase + (tid >> 3) + j * 32;
        aval[j] = r < M;
        aoffs[j] = aval[j] ? ((long)(r / a_seg) * a_outer + a_off + (r % a_seg)) * (long)lda : 0;
    }
    const __half* bgp = Bt + (size_t)(blockIdx.x * 128 + (tid >> 3)) * ldb + kc;

    const uint32_t ua = smem_u32(smh);
    uint32_t s_dst[4];
    #pragma unroll
    for (int j = 0; j < 4; j++)
        s_dst[j] = (uint32_t)(((((tid >> 3) + j * 32) * PH + kc)) * 2);

    const int lmoff = ((lane & 7) + ((lane >> 3) & 1) * 8) * PH + ((lane >> 4) & 1) * 8;

    uint32_t abase[3], bbase[3];
    #pragma unroll
    for (int s = 0; s < 3; s++) {
        abase[s] = ua + (uint32_t)(s * STG_H * 2) + (uint32_t)((wm * 32 * PH + lmoff) * 2);
        bbase[s] = ua + (uint32_t)(s * STG_H * 2) + (uint32_t)(A_STGH * 2)
                 + (uint32_t)((wn * 64 * PH + lmoff) * 2);
    }

    float acc[2][8][4];
    #pragma unroll
    for (int mt = 0; mt < 2; mt++)
        #pragma unroll
        for (int nt = 0; nt < 8; nt++)
            #pragma unroll
            for (int i = 0; i < 4; i++) acc[mt][nt][i] = 0.f;

    #pragma unroll
    for (int s = 0; s < 2; s++) {
        uint32_t sb_ = ua + (uint32_t)(s * STG_H * 2);
        int k0 = s * GBK;
        #pragma unroll
        for (int j = 0; j < 4; j++)
            cp16(sb_ + s_dst[j], A + aoffs[j] + k0 + kc, aval[j]);
        #pragma unroll
        for (int j = 0; j < 4; j++)
            cp16(sb_ + (uint32_t)(A_STGH * 2) + s_dst[j], bgp + (size_t)j * 32 * ldb + k0, true);
        cp_commit();
    }

    int buf = 0, wbuf = 2;
    for (int it = 0; it < niter; it++) {
        asm volatile("cp.async.wait_group 1;" ::: "memory");
        __syncthreads();
        if (it + 2 < niter) {
            uint32_t sb_ = ua + (uint32_t)(wbuf * STG_H * 2);
            int k0 = (it + 2) * GBK;
            #pragma unroll
            for (int j = 0; j < 4; j++)
                cp16(sb_ + s_dst[j], A + aoffs[j] + k0 + kc, aval[j]);
            #pragma unroll
            for (int j = 0; j < 4; j++)
                cp16(sb_ + (uint32_t)(A_STGH * 2) + s_dst[j], bgp + (size_t)j * 32 * ldb + k0, true);
        }
        cp_commit();

        const uint32_t ab = abase[buf];
        const uint32_t bb = bbase[buf];
        #pragma unroll
        for (int ks = 0; ks < 4; ks++) {
            unsigned afr[2][4];
            ldm4(afr[0], ab + (uint32_t)(ks * 16 * 2));
            ldm4(afr[1], ab + (uint32_t)((16 * PH + ks * 16) * 2));
            unsigned br[4][4];
            #pragma unroll
            for (int p = 0; p < 4; p++)
                ldm4(br[p], bb + (uint32_t)((p * 16 * PH + ks * 16) * 2));
            #pragma unroll
            for (int mt = 0; mt < 2; mt++)
                #pragma unroll
                for (int p = 0; p < 4; p++) {
                    HMMA(acc[mt][2*p],   afr[mt][0], afr[mt][1], afr[mt][2], afr[mt][3],
                         br[p][0], br[p][2]);
                    HMMA(acc[mt][2*p+1], afr[mt][0], afr[mt][1], afr[mt][2], afr[mt][3],
                         br[p][1], br[p][3]);
                }
        }
        buf  = (buf  == 2) ? 0 : buf + 1;
        wbuf = (wbuf == 2) ? 0 : wbuf + 1;
    }

    #pragma unroll
    for (int mt = 0; mt < 2; mt++) {
        #pragma unroll
        for (int half = 0; half < 2; half++) {
            int r = rowBase + wm * 32 + mt * 16 + gg + half * 8;
            if (r >= M) continue;
            long crow = (long)(r / c_seg) * c_outer + c_off + (r % c_seg);
            if (half_out) {
                __half* cp = (__half*)Cv + crow * ldc + colC + wn * 64 + 2 * t;
                #pragma unroll
                for (int nt = 0; nt < 8; nt++) {
                    __half2 v = __floats2half2_rn(acc[mt][nt][half * 2], acc[mt][nt][half * 2 + 1]);
                    *(__half2*)(cp + nt * 8) = v;
                }
            } else {
                float* cp = (float*)Cv + crow * ldc + colC + wn * 64 + 2 * t;
                #pragma unroll
                for (int nt = 0; nt < 8; nt++)
                    *(float2*)(cp + nt * 8) = make_float2(acc[mt][nt][half * 2],
                                                          acc[mt][nt][half * 2 + 1]);
            }
        }
    }
}

// ---------------- RoPE on half (q and k fused; q folds 1/16) ----------------
__global__ void rope2_kernel(__half* __restrict__ q, __half* __restrict__ k) {
    int bn = blockIdx.x;
    int h  = blockIdx.y;
    int n  = bn % Nc;
    int i  = threadIdx.x;
    size_t off = ((size_t)bn * Hc + h) * DHc;
    float inv_ts = exp2f(-13.287712379549449f * ((float)i * (1.0f / 128.0f)));
    float rad = (float)n * inv_ts;
    float s, c;
    sincosf(rad, &s, &c);
    __half* pq = q + off;
    float qa = __half2float(pq[i]), qb = __half2float(pq[i + 128]);
    pq[i]       = __float2half_rn((qa * c - qb * s) * 0.0625f);
    pq[i + 128] = __float2half_rn((qb * c + qa * s) * 0.0625f);
    __half* pk = k + off;
    float ka = __half2float(pk[i]), kb2 = __half2float(pk[i + 128]);
    pk[i]       = __float2half_rn(ka * c - kb2 * s);
    pk[i + 128] = __float2half_rn(kb2 * c + ka * s);
}

// ---------------- FP16 flash attention (identical to R14) ----------------
#define AQT 64
#define AKT 32
#define PA  264
#define ATH 128
#define KVSTR (2 * AKT * PA)
#define ATTN_SMEM ((AQT + 4 * AKT) * PA * 2)

__device__ __forceinline__ int row_kmax(int qi) {
    if (qi >= Nc) return 0;
    return (qi < L1c) ? L1c : ((qi == L1c) ? (L1c + 1) : Nc);
}

__global__ __launch_bounds__(ATH, 2) void attn_kernel(
    const __half* __restrict__ q, const __half* __restrict__ k,
    const __half* __restrict__ v, __half* __restrict__ o, int bh_base)
{
    extern __shared__ __half smh[];
    __half* Qs = smh;
    __half* KV = Qs + AQT * PA;

    const int bh = bh_base + blockIdx.y;
    const int b = bh >> 3, h = bh & 7;
    const int qBase = blockIdx.x * AQT;
    const int tid = threadIdx.x;
    const int lane = tid & 31, warp = tid >> 5;
    const int g = lane >> 2, t = lane & 3;
    const size_t bhoff = (size_t)b * Nc * HDc + (size_t)h * DHc;

    const uint32_t uq  = smem_u32(Qs);
    const uint32_t ukv = smem_u32(KV);

    #pragma unroll
    for (int j = 0; j < 16; j++) {
        int i = tid + j * ATH;
        int r = i >> 5, c8 = (i & 31) * 8;
        int qi = qBase + r;
        cp16(uq + (uint32_t)((r * PA + c8) * 2), q + bhoff + (size_t)qi * HDc + c8, qi < Nc);
    }
    cp_commit();

    const int qrow = warp * 16;
    const int qi0 = qBase + qrow + g;
    const int qi1 = qi0 + 8;
    const int kmax0 = row_kmax(qi0);
    const int kmax1 = row_kmax(qi1);

    float m0 = -1e30f, m1 = -1e30f, l0 = 0.f, l1 = 0.f;
    float acc[32][4];
    #pragma unroll
    for (int nt = 0; nt < 32; nt++)
        #pragma unroll
        for (int i = 0; i < 4; i++) acc[nt][i] = 0.f;

    const int qlast = min(qBase + AQT - 1, Nc - 1);
    const int kb = (qlast < L1c) ? L1c : ((qlast == L1c) ? (L1c + 1) : Nc);
    const int ntiles = (kb + AKT - 1) / AKT;

    const int lmoff = ((lane & 7) + ((lane >> 3) & 1) * 8) * PA + ((lane >> 4) & 1) * 8;
    const uint32_t qbase = uq + (uint32_t)((qrow * PA + lmoff) * 2);

    {
        uint32_t dst = ukv;
        #pragma unroll
        for (int j = 0; j < 8; j++) {
            int i = tid + j * ATH;
            int r = i >> 5, c8 = (i & 31) * 8;
            bool pv = r < Nc;
            cp16(dst + (uint32_t)((r * PA + c8) * 2), k + bhoff + (size_t)r * HDc + c8, pv);
            cp16(dst + (uint32_t)(((AKT + r) * PA + c8) * 2), v + bhoff + (size_t)r * HDc + c8, pv);
        }
        cp_commit();
    }

    for (int it = 0; it < ntiles; it++) {
        if (it + 1 < ntiles) {
            uint32_t dst = ukv + (uint32_t)(((it + 1) & 1) * KVSTR * 2);
            int k0n = (it + 1) * AKT;
            #pragma unroll
            for (int j = 0; j < 8; j++) {
                int i = tid + j * ATH;
                int r = i >> 5, c8 = (i & 31) * 8;
                int ki = k0n + r;
                bool pv = ki < Nc;
                cp16(dst + (uint32_t)((r * PA + c8) * 2), k + bhoff + (size_t)ki * HDc + c8, pv);
                cp16(dst + (uint32_t)(((AKT + r) * PA + c8) * 2), v + bhoff + (size_t)ki * HDc + c8, pv);
            }
        }
        cp_commit();
        asm volatile("cp.async.wait_group 1;" ::: "memory");
        __syncthreads();

        const int k0 = it * AKT;
        const uint32_t kbase = ukv + (uint32_t)((it & 1) * KVSTR * 2) + (uint32_t)(lmoff * 2);
        const uint32_t vbase = kbase + (uint32_t)(AKT * PA * 2);

        float sc[4][4];
        #pragma unroll
        for (int nt = 0; nt < 4; nt++)
            #pragma unroll
            for (int i = 0; i < 4; i++) sc[nt][i] = 0.f;

        #pragma unroll
        for (int ks = 0; ks < 16; ks++) {
            unsigned aq[4];
            ldm4(aq, qbase + (uint32_t)(ks * 16 * 2));
            unsigned bk[2][4];
            ldm4(bk[0], kbase + (uint32_t)((ks * 16) * 2));
            ldm4(bk[1], kbase + (uint32_t)((16 * PA + ks * 16) * 2));
            #pragma unroll
            for (int p = 0; p < 2; p++) {
                HMMA(sc[2*p],   aq[0], aq[1], aq[2], aq[3], bk[p][0], bk[p][2]);
                HMMA(sc[2*p+1], aq[0], aq[1], aq[2], aq[3], bk[p][1], bk[p][3]);
            }
        }

        #pragma unroll
        for (int nt = 0; nt < 4; nt++) {
            int key = k0 + nt * 8 + 2 * t;
            if (key     >= kmax0) sc[nt][0] = -1e30f;
            if (key + 1 >= kmax0) sc[nt][1] = -1e30f;
            if (key     >= kmax1) sc[nt][2] = -1e30f;
            if (key + 1 >= kmax1) sc[nt][3] = -1e30f;
        }
        float rmax0 = -1e30f, rmax1 = -1e30f;
        #pragma unroll
        for (int nt = 0; nt < 4; nt++) {
            rmax0 = fmaxf(rmax0, fmaxf(sc[nt][0], sc[nt][1]));
            rmax1 = fmaxf(rmax1, fmaxf(sc[nt][2], sc[nt][3]));
        }
        #pragma unroll
        for (int off = 1; off <= 2; off <<= 1) {
            rmax0 = fmaxf(rmax0, __shfl_xor_sync(0xffffffffu, rmax0, off));
            rmax1 = fmaxf(rmax1, __shfl_xor_sync(0xffffffffu, rmax1, off));
        }
        float nm0 = fmaxf(m0, rmax0), nm1 = fmaxf(m1, rmax1);
        float corr0 = __expf(m0 - nm0), corr1 = __expf(m1 - nm1);
        m0 = nm0; m1 = nm1;

        float pr[4][4];
        float psum0 = 0.f, psum1 = 0.f;
        #pragma unroll
        for (int nt = 0; nt < 4; nt++) {
            pr[nt][0] = __expf(sc[nt][0] - nm0);
            pr[nt][1] = __expf(sc[nt][1] - nm0);
            pr[nt][2] = __expf(sc[nt][2] - nm1);
            pr[nt][3] = __expf(sc[nt][3] - nm1);
            psum0 += pr[nt][0] + pr[nt][1];
            psum1 += pr[nt][2] + pr[nt][3];
        }
        l0 = l0 * corr0 + psum0;
        l1 = l1 * corr1 + psum1;
        #pragma unroll
        for (int nt = 0; nt < 32; nt++) {
            acc[nt][0] *= corr0; acc[nt][1] *= corr0;
            acc[nt][2] *= corr1; acc[nt][3] *= corr1;
        }

        #pragma unroll
        for (int kc2 = 0; kc2 < 2; kc2++) {
            unsigned pa0 = h2u(pr[2*kc2][0],   pr[2*kc2][1]);
            unsigned pa1 = h2u(pr[2*kc2][2],   pr[2*kc2][3]);
            unsigned pa2 = h2u(pr[2*kc2+1][0], pr[2*kc2+1][1]);
            unsigned pa3 = h2u(pr[2*kc2+1][2], pr[2*kc2+1][3]);
            #pragma unroll
            for (int nt2 = 0; nt2 < 16; nt2++) {
                unsigned bv[4];
                ldm4t(bv, vbase + (uint32_t)((kc2 * 16 * PA + nt2 * 16) * 2));
                HMMA(acc[2*nt2],   pa0, pa1, pa2, pa3, bv[0], bv[1]);
                HMMA(acc[2*nt2+1], pa0, pa1, pa2, pa3, bv[2], bv[3]);
            }
        }
        __syncthreads();
    }

    l0 += __shfl_xor_sync(0xffffffffu, l0, 1);
    l0 += __shfl_xor_sync(0xffffffffu, l0, 2);
    l1 += __shfl_xor_sync(0xffffffffu, l1, 1);
    l1 += __shfl_xor_sync(0xffffffffu, l1, 2);

    float inv0 = 1.0f / l0, inv1 = 1.0f / l1;
    if (qi0 < Nc) {
        __half* op = o + bhoff + (size_t)qi0 * HDc + 2 * t;
        #pragma unroll
        for (int nt = 0; nt < 32; nt++)
            *(__half2*)(op + nt * 8) = __floats2half2_rn(acc[nt][0] * inv0, acc[nt][1] * inv0);
    }
    if (qi1 < Nc) {
        __half* op = o + bhoff + (size_t)qi1 * HDc + 2 * t;
        #pragma unroll
        for (int nt = 0; nt < 32; nt++)
            *(__half2*)(op + nt * 8) = __floats2half2_rn(acc[nt][2] * inv1, acc[nt][3] * inv1);
    }
}

// ---------------- Host launch ----------------
extern "C" void kernel_launch(void* const* d_in, const int* in_sizes, int n_in,
                              void* d_out, int out_size) {
    const float* x1   = (const float*)d_in[0];
    const float* x2   = (const float*)d_in[1];
    const float* ln1w = (const float*)d_in[2];
    const float* ln2w = (const float*)d_in[3];
    const float* Wq1  = (const float*)d_in[4];
    const float* Wk1  = (const float*)d_in[5];
    const float* Wv1  = (const float*)d_in[6];
    const float* Wo1  = (const float*)d_in[7];
    const float* Wq2  = (const float*)d_in[8];
    const float* Wk2  = (const float*)d_in[9];
    const float* Wv2  = (const float*)d_in[10];
    const float* Wo2  = (const float*)d_in[11];

    static __half *h1p = nullptr, *h2p = nullptr, *qp = nullptr, *kp = nullptr,
                  *vp = nullptr, *aop = nullptr, *wtp = nullptr;
    static cudaStream_t s2 = nullptr, s3 = nullptr;
    static cudaEvent_t ev[12];
    static bool inited = false;
    if (!inited) {
        cudaGetSymbolAddress((void**)&h1p, g_h1h);
        cudaGetSymbolAddress((void**)&h2p, g_h2h);
        cudaGetSymbolAddress((void**)&qp,  g_qh);
        cudaGetSymbolAddress((void**)&kp,  g_kh);
        cudaGetSymbolAddress((void**)&vp,  g_vh);
        cudaGetSymbolAddress((void**)&aop, g_aoh);
        cudaGetSymbolAddress((void**)&wtp, g_wth);
        cudaStreamCreateWithFlags(&s2, cudaStreamNonBlocking);
        cudaStreamCreateWithFlags(&s3, cudaStreamNonBlocking);
        for (int i = 0; i < 12; i++)
            cudaEventCreateWithFlags(&ev[i], cudaEventDisableTiming);
        cudaFuncSetAttribute(attn_kernel,
                             cudaFuncAttributeMaxDynamicSharedMemorySize, ATTN_SMEM);
        cudaFuncSetAttribute(hgemm_kernel,
                             cudaFuncAttributeMaxDynamicSharedMemorySize, G_SMEM);
        inited = true;
    }

    float* outp = (float*)d_out;
    const int M1 = Bc * L1c;   // 13056
    const int M2 = Bc * L2c;   // 816
    const int MQ = 4 * L1c;    // 3264  (Wo1 quarter: 4 batches)

    __half* Wqkv1T = wtp;
    __half* Wqkv2T = Wqkv1T + (size_t)6144 * 2048;
    __half* Wo1T   = Wqkv2T + (size_t)6144 * 1024;
    __half* Wo2T   = Wo1T   + (size_t)2048 * 2048;

    dim3 tb(32, 8);
    cudaStream_t s1 = 0;

    // ---- fork: s2 (stream-2 pipeline + Wo weights), s3 (rmsnorm1) ----
    cudaEventRecord(ev[0], s1);
    cudaStreamWaitEvent(s2, ev[0], 0);
    cudaStreamWaitEvent(s3, ev[0], 0);

    // s3: rmsnorm1 (off s1's critical path)
    rmsnorm_kernel<<<M1, 256, 0, s3>>>(x1, ln1w, h1p, D1c);
    cudaEventRecord(ev[1], s3);

    // s1: QKV1 weights, then QKV1 GEMM (waits on rmsnorm1)
    qkv_transround_kernel<<<dim3(HDc/32, D1c/32, 3), tb, 0, s1>>>(Wq1, Wk1, Wv1, Wqkv1T, D1c, HDc);
    cudaStreamWaitEvent(s1, ev[1], 0);
    dim3 gq1(48, M1 / 128);
    hgemm_kernel<<<gq1, 256, G_SMEM, s1>>>(h1p, D1c, Wqkv1T, D1c, qp, kp, vp, HDc,
                                           M1, D1c, M1, 0, 0, L1c, Nc, 0, 16, 1);

    // s2: stream-2 prep + QKV2, then Wo weights in the idle window
    qkv_transround_kernel<<<dim3(HDc/32, D2c/32, 3), tb, 0, s2>>>(Wq2, Wk2, Wv2, Wqkv2T, D2c, HDc);
    rmsnorm_kernel<<<M2, 256, 0, s2>>>(x2, ln2w, h2p, D2c);
    dim3 gq2(48, (M2 + 127) / 128);
    hgemm_kernel<<<gq2, 256, G_SMEM, s2>>>(h2p, D2c, Wqkv2T, D2c, qp, kp, vp, HDc,
                                           M2, D2c, M2, 0, 0, L2c, Nc, L1c, 16, 1);
    cudaEventRecord(ev[2], s2);                      // QKV2 done (for rope)
    transround_kernel<<<dim3(D1c/32, HDc/32), tb, 0, s2>>>(Wo1, Wo1T, HDc, D1c);
    transround_kernel<<<dim3(D2c/32, HDc/32), tb, 0, s2>>>(Wo2, Wo2T, HDc, D2c);

    // ---- rope (needs QKV1 on s1 + QKV2 via ev[2]) ----
    cudaStreamWaitEvent(s1, ev[2], 0);
    dim3 gr(Bc * Nc, Hc);
    rope2_kernel<<<gr, 128, 0, s1>>>(qp, kp);

    // ---- attention in batch quarters; rolling Wo1 overlap on s2 ----
    dim3 gaq(14, 32);   // 4 batches per quarter
    for (int qd = 0; qd < 4; qd++) {
        attn_kernel<<<gaq, ATH, ATTN_SMEM, s1>>>(qp, kp, vp, aop, qd * 32);
        cudaEventRecord(ev[3 + qd], s1);
    }

    // s2: Wo1 quarters 0..2 as their attention finishes; Wo2 after quarter 3
    dim3 goq(16, (MQ + 127) / 128);   // (16, 26)
    for (int qd = 0; qd < 3; qd++) {
        cudaStreamWaitEvent(s2, ev[3 + qd], 0);
        hgemm_kernel<<<goq, 256, G_SMEM, s2>>>(aop, HDc, Wo1T, HDc, outp, outp, outp, D1c,
                                               MQ, HDc, L1c, Nc, qd * 4 * Nc,
                                               MQ, 0, qd * 4 * L1c, 16, 0);
    }
    cudaStreamWaitEvent(s2, ev[6], 0);
    dim3 go2(8, (M2 + 127) / 128);
    hgemm_kernel<<<go2, 256, G_SMEM, s2>>>(aop, HDc, Wo2T, HDc,
                                           outp + (size_t)Bc * L1c * D1c,
                                           outp + (size_t)Bc * L1c * D1c,
                                           outp + (size_t)Bc * L1c * D1c, D2c,
                                           M2, HDc, L2c, Nc, L1c, M2, 0, 0, 8, 0);

    // s1: Wo1 quarter 3 (batches 12-15)
    hgemm_kernel<<<goq, 256, G_SMEM, s1>>>(aop, HDc, Wo1T, HDc, outp, outp, outp, D1c,
                                           MQ, HDc, L1c, Nc, 12 * Nc,
                                           MQ, 0, 12 * L1c, 16, 0);

    // ---- join ----
    cudaEventRecord(ev[7], s2);
    cudaStreamWaitEvent(s1, ev[7], 0);
}

// round 16
// speedup vs baseline: 1.5649x; 1.5649x over previous
#include <cuda_runtime.h>
#include <cuda_fp16.h>
#include <math.h>
#include <stdint.h>

// Problem constants
#define Bc   16
#define L1c  816
#define L2c  51
#define Nc   867
#define Hc   8
#define DHc  256
#define D1c  2048
#define D2c  1024
#define HDc  2048

// ---------------- Scratch (half precision pipeline) ----------------
__device__ __half g_h1h[(size_t)Bc * L1c * D1c];
__device__ __half g_h2h[(size_t)Bc * L2c * D2c];
__device__ __half g_qh [(size_t)Bc * Nc  * HDc];
__device__ __half g_kh [(size_t)Bc * Nc  * HDc];
__device__ __half g_vh [(size_t)Bc * Nc  * HDc];
__device__ __half g_aoh[(size_t)Bc * Nc  * HDc];
__device__ __half g_wth[(size_t)6144*2048 + 6144*1024 + 2048*2048 + 1024*2048];

__device__ __forceinline__ uint32_t smem_u32(const void* p) {
    uint32_t a;
    asm("{ .reg .u64 t; cvta.to.shared.u64 t, %1; cvt.u32.u64 %0, t; }" : "=r"(a) : "l"(p));
    return a;
}
__device__ __forceinline__ void cp16(uint32_t dst, const void* src, bool pred) {
    int sz = pred ? 16 : 0;
    asm volatile("cp.async.cg.shared.global [%0], [%1], 16, %2;"
                 :: "r"(dst), "l"(src), "r"(sz) : "memory");
}
__device__ __forceinline__ void cp_commit() {
    asm volatile("cp.async.commit_group;" ::: "memory");
}
__device__ __forceinline__ void ldm4(unsigned* a, uint32_t addr) {
    asm volatile("ldmatrix.sync.aligned.m8n8.x4.shared.b16 {%0,%1,%2,%3}, [%4];"
                 : "=r"(a[0]), "=r"(a[1]), "=r"(a[2]), "=r"(a[3]) : "r"(addr));
}
__device__ __forceinline__ void ldm4t(unsigned* a, uint32_t addr) {
    asm volatile("ldmatrix.sync.aligned.m8n8.x4.trans.shared.b16 {%0,%1,%2,%3}, [%4];"
                 : "=r"(a[0]), "=r"(a[1]), "=r"(a[2]), "=r"(a[3]) : "r"(addr));
}
#define HMMA(acc, a0,a1,a2,a3, b0,b1) \
    asm volatile( \
        "mma.sync.aligned.m16n8k16.row.col.f32.f16.f16.f32 " \
        "{%0,%1,%2,%3}, {%4,%5,%6,%7}, {%8,%9}, {%0,%1,%2,%3};" \
        : "+f"((acc)[0]), "+f"((acc)[1]), "+f"((acc)[2]), "+f"((acc)[3]) \
        : "r"(a0), "r"(a1), "r"(a2), "r"(a3), "r"(b0), "r"(b1))

__device__ __forceinline__ unsigned h2u(float lo, float hi) {
    __half2 h = __floats2half2_rn(lo, hi);
    return *(unsigned*)&h;
}

// ---------------- Round + transpose to half: out[n][k] = h(in[k][n]) ----------------
__global__ void transround_kernel(const float* __restrict__ in, __half* __restrict__ out,
                                  int K, int N) {
    __shared__ float tile[32][33];
    int nb = blockIdx.x * 32, kb = blockIdx.y * 32;
    int tx = threadIdx.x, ty = threadIdx.y;
    #pragma unroll
    for (int j = 0; j < 4; j++)
        tile[ty + j * 8][tx] = in[(size_t)(kb + ty + j * 8) * N + nb + tx];
    __syncthreads();
    #pragma unroll
    for (int j = 0; j < 4; j++)
        out[(size_t)(nb + ty + j * 8) * K + kb + tx] = __float2half_rn(tile[tx][ty + j * 8]);
}

__global__ void qkv_transround_kernel(const float* __restrict__ wq,
                                      const float* __restrict__ wk,
                                      const float* __restrict__ wv,
                                      __half* __restrict__ out, int K, int N) {
    __shared__ float tile[32][33];
    const float* in = (blockIdx.z == 0) ? wq : ((blockIdx.z == 1) ? wk : wv);
    __half* dst = out + (size_t)blockIdx.z * N * K;
    int nb = blockIdx.x * 32, kb = blockIdx.y * 32;
    int tx = threadIdx.x, ty = threadIdx.y;
    #pragma unroll
    for (int j = 0; j < 4; j++)
        tile[ty + j * 8][tx] = in[(size_t)(kb + ty + j * 8) * N + nb + tx];
    __syncthreads();
    #pragma unroll
    for (int j = 0; j < 4; j++)
        dst[(size_t)(nb + ty + j * 8) * K + kb + tx] = __float2half_rn(tile[tx][ty + j * 8]);
}

// ---------------- RMSNorm (writes half) ----------------
__global__ void rmsnorm_kernel(const float* __restrict__ x, const float* __restrict__ w,
                               __half* __restrict__ out, int D) {
    int row = blockIdx.x;
    const float* xr = x + (size_t)row * D;
    __half* orow = out + (size_t)row * D;
    float ss = 0.f;
    for (int d = threadIdx.x; d < D; d += blockDim.x) {
        float v = xr[d];
        ss += v * v;
    }
    __shared__ float red[256];
    red[threadIdx.x] = ss;
    __syncthreads();
    for (int s = 128; s > 0; s >>= 1) {
        if (threadIdx.x < s) red[threadIdx.x] += red[threadIdx.x + s];
        __syncthreads();
    }
    float scale = rsqrtf(red[0] / (float)D + 1e-6f);
    for (int d = threadIdx.x; d < D; d += blockDim.x)
        orow[d] = __float2half_rn(xr[d] * scale * (1.0f + w[d]));
}

// ---------------- FP16 GEMM (identical to R14) ----------------
#define GBK 64
#define PH  72
#define A_STGH (128 * PH)
#define STG_H  (2 * A_STGH)
#define G_SMEM (3 * STG_H * 2)

__global__ __launch_bounds__(256, 2) void hgemm_kernel(
    const __half* __restrict__ A, int lda,
    const __half* __restrict__ Bt, int ldb,
    void* C0v, void* C1v, void* C2v, int ldc,
    int M, int K,
    int a_seg, int a_outer, int a_off,
    int c_seg, int c_outer, int c_off,
    int blocks_per_out, int half_out)
{
    extern __shared__ __half smh[];
    const int tid  = threadIdx.x;
    const int lane = tid & 31;
    const int warp = tid >> 5;
    const int wm   = warp >> 1;
    const int wn   = warp & 1;
    const int gg   = lane >> 2;
    const int t    = lane & 3;

    const int out = blockIdx.x / blocks_per_out;
    void* Cv = (out == 0) ? C0v : ((out == 1) ? C1v : C2v);
    const int colC = (blockIdx.x % blocks_per_out) * 128;
    const int rowBase = blockIdx.y * 128;
    const int niter = K / GBK;

    const int kc = (tid & 7) * 8;
    long aoffs[4];
    bool aval[4];
    #pragma unroll
    for (int j = 0; j < 4; j++) {
        int r = rowBase + (tid >> 3) + j * 32;
        aval[j] = r < M;
        aoffs[j] = aval[j] ? ((long)(r / a_seg) * a_outer + a_off + (r % a_seg)) * (long)lda : 0;
    }
    const __half* bgp = Bt + (size_t)(blockIdx.x * 128 + (tid >> 3)) * ldb + kc;

    const uint32_t ua = smem_u32(smh);
    uint32_t s_dst[4];
    #pragma unroll
    for (int j = 0; j < 4; j++)
        s_dst[j] = (uint32_t)(((((tid >> 3) + j * 32) * PH + kc)) * 2);

    const int lmoff = ((lane & 7) + ((lane >> 3) & 1) * 8) * PH + ((lane >> 4) & 1) * 8;

    uint32_t abase[3], bbase[3];
    #pragma unroll
    for (int s = 0; s < 3; s++) {
        abase[s] = ua + (uint32_t)(s * STG_H * 2) + (uint32_t)((wm * 32 * PH + lmoff) * 2);
        bbase[s] = ua + (uint32_t)(s * STG_H * 2) + (uint32_t)(A_STGH * 2)
                 + (uint32_t)((wn * 64 * PH + lmoff) * 2);
    }

    float acc[2][8][4];
    #pragma unroll
    for (int mt = 0; mt < 2; mt++)
        #pragma unroll
        for (int nt = 0; nt < 8; nt++)
            #pragma unroll
            for (int i = 0; i < 4; i++) acc[mt][nt][i] = 0.f;

    #pragma unroll
    for (int s = 0; s < 2; s++) {
        uint32_t sb_ = ua + (uint32_t)(s * STG_H * 2);
        int k0 = s * GBK;
        #pragma unroll
        for (int j = 0; j < 4; j++)
            cp16(sb_ + s_dst[j], A + aoffs[j] + k0 + kc, aval[j]);
        #pragma unroll
        for (int j = 0; j < 4; j++)
            cp16(sb_ + (uint32_t)(A_STGH * 2) + s_dst[j], bgp + (size_t)j * 32 * ldb + k0, true);
        cp_commit();
    }

    int buf = 0, wbuf = 2;
    for (int it = 0; it < niter; it++) {
        asm volatile("cp.async.wait_group 1;" ::: "memory");
        __syncthreads();
        if (it + 2 < niter) {
            uint32_t sb_ = ua + (uint32_t)(wbuf * STG_H * 2);
            int k0 = (it + 2) * GBK;
            #pragma unroll
            for (int j = 0; j < 4; j++)
                cp16(sb_ + s_dst[j], A + aoffs[j] + k0 + kc, aval[j]);
            #pragma unroll
            for (int j = 0; j < 4; j++)
                cp16(sb_ + (uint32_t)(A_STGH * 2) + s_dst[j], bgp + (size_t)j * 32 * ldb + k0, true);
        }
        cp_commit();

        const uint32_t ab = abase[buf];
        const uint32_t bb = bbase[buf];
        #pragma unroll
        for (int ks = 0; ks < 4; ks++) {
            unsigned afr[2][4];
            ldm4(afr[0], ab + (uint32_t)(ks * 16 * 2));
            ldm4(afr[1], ab + (uint32_t)((16 * PH + ks * 16) * 2));
            unsigned br[4][4];
            #pragma unroll
            for (int p = 0; p < 4; p++)
                ldm4(br[p], bb + (uint32_t)((p * 16 * PH + ks * 16) * 2));
            #pragma unroll
            for (int mt = 0; mt < 2; mt++)
                #pragma unroll
                for (int p = 0; p < 4; p++) {
                    HMMA(acc[mt][2*p],   afr[mt][0], afr[mt][1], afr[mt][2], afr[mt][3],
                         br[p][0], br[p][2]);
                    HMMA(acc[mt][2*p+1], afr[mt][0], afr[mt][1], afr[mt][2], afr[mt][3],
                         br[p][1], br[p][3]);
                }
        }
        buf  = (buf  == 2) ? 0 : buf + 1;
        wbuf = (wbuf == 2) ? 0 : wbuf + 1;
    }

    #pragma unroll
    for (int mt = 0; mt < 2; mt++) {
        #pragma unroll
        for (int half = 0; half < 2; half++) {
            int r = rowBase + wm * 32 + mt * 16 + gg + half * 8;
            if (r >= M) continue;
            long crow = (long)(r / c_seg) * c_outer + c_off + (r % c_seg);
            if (half_out) {
                __half* cp = (__half*)Cv + crow * ldc + colC + wn * 64 + 2 * t;
                #pragma unroll
                for (int nt = 0; nt < 8; nt++) {
                    __half2 v = __floats2half2_rn(acc[mt][nt][half * 2], acc[mt][nt][half * 2 + 1]);
                    *(__half2*)(cp + nt * 8) = v;
                }
            } else {
                float* cp = (float*)Cv + crow * ldc + colC + wn * 64 + 2 * t;
                #pragma unroll
                for (int nt = 0; nt < 8; nt++)
                    *(float2*)(cp + nt * 8) = make_float2(acc[mt][nt][half * 2],
                                                          acc[mt][nt][half * 2 + 1]);
            }
        }
    }
}

// ---------------- RoPE on half (q and k fused; q folds 1/16) ----------------
__global__ void rope2_kernel(__half* __restrict__ q, __half* __restrict__ k) {
    int bn = blockIdx.x;
    int h  = blockIdx.y;
    int n  = bn % Nc;
    int i  = threadIdx.x;
    size_t off = ((size_t)bn * Hc + h) * DHc;
    float inv_ts = exp2f(-13.287712379549449f * ((float)i * (1.0f / 128.0f)));
    float rad = (float)n * inv_ts;
    float s, c;
    sincosf(rad, &s, &c);
    __half* pq = q + off;
    float qa = __half2float(pq[i]), qb = __half2float(pq[i + 128]);
    pq[i]       = __float2half_rn((qa * c - qb * s) * 0.0625f);
    pq[i + 128] = __float2half_rn((qb * c + qa * s) * 0.0625f);
    __half* pk = k + off;
    float ka = __half2float(pk[i]), kb2 = __half2float(pk[i + 128]);
    pk[i]       = __float2half_rn(ka * c - kb2 * s);
    pk[i + 128] = __float2half_rn(kb2 * c + ka * s);
}

// ---------------- FP16 flash attention (identical to R14) ----------------
#define AQT 64
#define AKT 32
#define PA  264
#define ATH 128
#define KVSTR (2 * AKT * PA)
#define ATTN_SMEM ((AQT + 4 * AKT) * PA * 2)

__device__ __forceinline__ int row_kmax(int qi) {
    if (qi >= Nc) return 0;
    return (qi < L1c) ? L1c : ((qi == L1c) ? (L1c + 1) : Nc);
}

__global__ __launch_bounds__(ATH, 2) void attn_kernel(
    const __half* __restrict__ q, const __half* __restrict__ k,
    const __half* __restrict__ v, __half* __restrict__ o, int bh_base)
{
    extern __shared__ __half smh[];
    __half* Qs = smh;
    __half* KV = Qs + AQT * PA;

    const int bh = bh_base + blockIdx.y;
    const int b = bh >> 3, h = bh & 7;
    const int qBase = blockIdx.x * AQT;
    const int tid = threadIdx.x;
    const int lane = tid & 31, warp = tid >> 5;
    const int g = lane >> 2, t = lane & 3;
    const size_t bhoff = (size_t)b * Nc * HDc + (size_t)h * DHc;

    const uint32_t uq  = smem_u32(Qs);
    const uint32_t ukv = smem_u32(KV);

    #pragma unroll
    for (int j = 0; j < 16; j++) {
        int i = tid + j * ATH;
        int r = i >> 5, c8 = (i & 31) * 8;
        int qi = qBase + r;
        cp16(uq + (uint32_t)((r * PA + c8) * 2), q + bhoff + (size_t)qi * HDc + c8, qi < Nc);
    }
    cp_commit();

    const int qrow = warp * 16;
    const int qi0 = qBase + qrow + g;
    const int qi1 = qi0 + 8;
    const int kmax0 = row_kmax(qi0);
    const int kmax1 = row_kmax(qi1);

    float m0 = -1e30f, m1 = -1e30f, l0 = 0.f, l1 = 0.f;
    float acc[32][4];
    #pragma unroll
    for (int nt = 0; nt < 32; nt++)
        #pragma unroll
        for (int i = 0; i < 4; i++) acc[nt][i] = 0.f;

    const int qlast = min(qBase + AQT - 1, Nc - 1);
    const int kb = (qlast < L1c) ? L1c : ((qlast == L1c) ? (L1c + 1) : Nc);
    const int ntiles = (kb + AKT - 1) / AKT;

    const int lmoff = ((lane & 7) + ((lane >> 3) & 1) * 8) * PA + ((lane >> 4) & 1) * 8;
    const uint32_t qbase = uq + (uint32_t)((qrow * PA + lmoff) * 2);

    {
        uint32_t dst = ukv;
        #pragma unroll
        for (int j = 0; j < 8; j++) {
            int i = tid + j * ATH;
            int r = i >> 5, c8 = (i & 31) * 8;
            bool pv = r < Nc;
            cp16(dst + (uint32_t)((r * PA + c8) * 2), k + bhoff + (size_t)r * HDc + c8, pv);
            cp16(dst + (uint32_t)(((AKT + r) * PA + c8) * 2), v + bhoff + (size_t)r * HDc + c8, pv);
        }
        cp_commit();
    }

    for (int it = 0; it < ntiles; it++) {
        if (it + 1 < ntiles) {
            uint32_t dst = ukv + (uint32_t)(((it + 1) & 1) * KVSTR * 2);
            int k0n = (it + 1) * AKT;
            #pragma unroll
            for (int j = 0; j < 8; j++) {
                int i = tid + j * ATH;
                int r = i >> 5, c8 = (i & 31) * 8;
                int ki = k0n + r;
                bool pv = ki < Nc;
                cp16(dst + (uint32_t)((r * PA + c8) * 2), k + bhoff + (size_t)ki * HDc + c8, pv);
                cp16(dst + (uint32_t)(((AKT + r) * PA + c8) * 2), v + bhoff + (size_t)ki * HDc + c8, pv);
            }
        }
        cp_commit();
        asm volatile("cp.async.wait_group 1;" ::: "memory");
        __syncthreads();

        const int k0 = it * AKT;
        const uint32_t kbase = ukv + (uint32_t)((it & 1) * KVSTR * 2) + (uint32_t)(lmoff * 2);
        const uint32_t vbase = kbase + (uint32_t)(AKT * PA * 2);

        float sc[4][4];
        #pragma unroll
        for (int nt = 0; nt < 4; nt++)
            #pragma unroll
            for (int i = 0; i < 4; i++) sc[nt][i] = 0.f;

        #pragma unroll
        for (int ks = 0; ks < 16; ks++) {
            unsigned aq[4];
            ldm4(aq, qbase + (uint32_t)(ks * 16 * 2));
            unsigned bk[2][4];
            ldm4(bk[0], kbase + (uint32_t)((ks * 16) * 2));
            ldm4(bk[1], kbase + (uint32_t)((16 * PA + ks * 16) * 2));
            #pragma unroll
            for (int p = 0; p < 2; p++) {
                HMMA(sc[2*p],   aq[0], aq[1], aq[2], aq[3], bk[p][0], bk[p][2]);
                HMMA(sc[2*p+1], aq[0], aq[1], aq[2], aq[3], bk[p][1], bk[p][3]);
            }
        }

        #pragma unroll
        for (int nt = 0; nt < 4; nt++) {
            int key = k0 + nt * 8 + 2 * t;
            if (key     >= kmax0) sc[nt][0] = -1e30f;
            if (key + 1 >= kmax0) sc[nt][1] = -1e30f;
            if (key     >= kmax1) sc[nt][2] = -1e30f;
            if (key + 1 >= kmax1) sc[nt][3] = -1e30f;
        }
        float rmax0 = -1e30f, rmax1 = -1e30f;
        #pragma unroll
        for (int nt = 0; nt < 4; nt++) {
            rmax0 = fmaxf(rmax0, fmaxf(sc[nt][0], sc[nt][1]));
            rmax1 = fmaxf(rmax1, fmaxf(sc[nt][2], sc[nt][3]));
        }
        #pragma unroll
        for (int off = 1; off <= 2; off <<= 1) {
            rmax0 = fmaxf(rmax0, __shfl_xor_sync(0xffffffffu, rmax0, off));
            rmax1 = fmaxf(rmax1, __shfl_xor_sync(0xffffffffu, rmax1, off));
        }
        float nm0 = fmaxf(m0, rmax0), nm1 = fmaxf(m1, rmax1);
        float corr0 = __expf(m0 - nm0), corr1 = __expf(m1 - nm1);
        m0 = nm0; m1 = nm1;

        float pr[4][4];
        float psum0 = 0.f, psum1 = 0.f;
        #pragma unroll
        for (int nt = 0; nt < 4; nt++) {
            pr[nt][0] = __expf(sc[nt][0] - nm0);
            pr[nt][1] = __expf(sc[nt][1] - nm0);
            pr[nt][2] = __expf(sc[nt][2] - nm1);
            pr[nt][3] = __expf(sc[nt][3] - nm1);
            psum0 += pr[nt][0] + pr[nt][1];
            psum1 += pr[nt][2] + pr[nt][3];
        }
        l0 = l0 * corr0 + psum0;
        l1 = l1 * corr1 + psum1;
        #pragma unroll
        for (int nt = 0; nt < 32; nt++) {
            acc[nt][0] *= corr0; acc[nt][1] *= corr0;
            acc[nt][2] *= corr1; acc[nt][3] *= corr1;
        }

        #pragma unroll
        for (int kc2 = 0; kc2 < 2; kc2++) {
            unsigned pa0 = h2u(pr[2*kc2][0],   pr[2*kc2][1]);
            unsigned pa1 = h2u(pr[2*kc2][2],   pr[2*kc2][3]);
            unsigned pa2 = h2u(pr[2*kc2+1][0], pr[2*kc2+1][1]);
            unsigned pa3 = h2u(pr[2*kc2+1][2], pr[2*kc2+1][3]);
            #pragma unroll
            for (int nt2 = 0; nt2 < 16; nt2++) {
                unsigned bv[4];
                ldm4t(bv, vbase + (uint32_t)((kc2 * 16 * PA + nt2 * 16) * 2));
                HMMA(acc[2*nt2],   pa0, pa1, pa2, pa3, bv[0], bv[1]);
                HMMA(acc[2*nt2+1], pa0, pa1, pa2, pa3, bv[2], bv[3]);
            }
        }
        __syncthreads();
    }

    l0 += __shfl_xor_sync(0xffffffffu, l0, 1);
    l0 += __shfl_xor_sync(0xffffffffu, l0, 2);
    l1 += __shfl_xor_sync(0xffffffffu, l1, 1);
    l1 += __shfl_xor_sync(0xffffffffu, l1, 2);

    float inv0 = 1.0f / l0, inv1 = 1.0f / l1;
    if (qi0 < Nc) {
        __half* op = o + bhoff + (size_t)qi0 * HDc + 2 * t;
        #pragma unroll
        for (int nt = 0; nt < 32; nt++)
            *(__half2*)(op + nt * 8) = __floats2half2_rn(acc[nt][0] * inv0, acc[nt][1] * inv0);
    }
    if (qi1 < Nc) {
        __half* op = o + bhoff + (size_t)qi1 * HDc + 2 * t;
        #pragma unroll
        for (int nt = 0; nt < 32; nt++)
            *(__half2*)(op + nt * 8) = __floats2half2_rn(acc[nt][2] * inv1, acc[nt][3] * inv1);
    }
}

// ---------------- Host launch ----------------
extern "C" void kernel_launch(void* const* d_in, const int* in_sizes, int n_in,
                              void* d_out, int out_size) {
    const float* x1   = (const float*)d_in[0];
    const float* x2   = (const float*)d_in[1];
    const float* ln1w = (const float*)d_in[2];
    const float* ln2w = (const float*)d_in[3];
    const float* Wq1  = (const float*)d_in[4];
    const float* Wk1  = (const float*)d_in[5];
    const float* Wv1  = (const float*)d_in[6];
    const float* Wo1  = (const float*)d_in[7];
    const float* Wq2  = (const float*)d_in[8];
    const float* Wk2  = (const float*)d_in[9];
    const float* Wv2  = (const float*)d_in[10];
    const float* Wo2  = (const float*)d_in[11];

    static __half *h1p = nullptr, *h2p = nullptr, *qp = nullptr, *kp = nullptr,
                  *vp = nullptr, *aop = nullptr, *wtp = nullptr;
    static cudaStream_t s2 = nullptr, s3 = nullptr;
    static cudaEvent_t ev[8];
    static bool inited = false;
    if (!inited) {
        cudaGetSymbolAddress((void**)&h1p, g_h1h);
        cudaGetSymbolAddress((void**)&h2p, g_h2h);
        cudaGetSymbolAddress((void**)&qp,  g_qh);
        cudaGetSymbolAddress((void**)&kp,  g_kh);
        cudaGetSymbolAddress((void**)&vp,  g_vh);
        cudaGetSymbolAddress((void**)&aop, g_aoh);
        cudaGetSymbolAddress((void**)&wtp, g_wth);
        cudaStreamCreateWithFlags(&s2, cudaStreamNonBlocking);
        cudaStreamCreateWithFlags(&s3, cudaStreamNonBlocking);
        for (int i = 0; i < 8; i++)
            cudaEventCreateWithFlags(&ev[i], cudaEventDisableTiming);
        cudaFuncSetAttribute(attn_kernel,
                             cudaFuncAttributeMaxDynamicSharedMemorySize, ATTN_SMEM);
        cudaFuncSetAttribute(hgemm_kernel,
                             cudaFuncAttributeMaxDynamicSharedMemorySize, G_SMEM);
        inited = true;
    }

    float* outp = (float*)d_out;
    const int M1 = Bc * L1c;   // 13056
    const int M2 = Bc * L2c;   // 816
    const int M1h = M1 / 2;    // 6528

    __half* Wqkv1T = wtp;
    __half* Wqkv2T = Wqkv1T + (size_t)6144 * 2048;
    __half* Wo1T   = Wqkv2T + (size_t)6144 * 1024;
    __half* Wo2T   = Wo1T   + (size_t)2048 * 2048;

    dim3 tb(32, 8);
    cudaStream_t s1 = 0;

    // ---- fork: s2 (stream-2 pipeline), s3 (rmsnorm1) ----
    cudaEventRecord(ev[0], s1);
    cudaStreamWaitEvent(s2, ev[0], 0);
    cudaStreamWaitEvent(s3, ev[0], 0);

    // s3: rmsnorm1 concurrent with QKV1 weight transround
    rmsnorm_kernel<<<M1, 256, 0, s3>>>(x1, ln1w, h1p, D1c);
    cudaEventRecord(ev[1], s3);

    // s1: QKV1 weights, then QKV1 GEMM (waits for rmsnorm1)
    qkv_transround_kernel<<<dim3(HDc/32, D1c/32, 3), tb, 0, s1>>>(Wq1, Wk1, Wv1, Wqkv1T, D1c, HDc);
    cudaStreamWaitEvent(s1, ev[1], 0);
    dim3 gq1(48, M1 / 128);
    hgemm_kernel<<<gq1, 256, G_SMEM, s1>>>(h1p, D1c, Wqkv1T, D1c, qp, kp, vp, HDc,
                                           M1, D1c, M1, 0, 0, L1c, Nc, 0, 16, 1);

    // s2: stream-2 prep + QKV2, then Wo weights in the idle window
    qkv_transround_kernel<<<dim3(HDc/32, D2c/32, 3), tb, 0, s2>>>(Wq2, Wk2, Wv2, Wqkv2T, D2c, HDc);
    rmsnorm_kernel<<<M2, 256, 0, s2>>>(x2, ln2w, h2p, D2c);
    dim3 gq2(48, (M2 + 127) / 128);
    hgemm_kernel<<<gq2, 256, G_SMEM, s2>>>(h2p, D2c, Wqkv2T, D2c, qp, kp, vp, HDc,
                                           M2, D2c, M2, 0, 0, L2c, Nc, L1c, 16, 1);
    cudaEventRecord(ev[2], s2);                      // QKV2 done (for rope)
    transround_kernel<<<dim3(D1c/32, HDc/32), tb, 0, s2>>>(Wo1, Wo1T, HDc, D1c);
    transround_kernel<<<dim3(D2c/32, HDc/32), tb, 0, s2>>>(Wo2, Wo2T, HDc, D2c);

    // ---- rope (needs QKV1 on s1 + QKV2 via ev[2]) ----
    cudaStreamWaitEvent(s1, ev[2], 0);
    dim3 gr(Bc * Nc, Hc);
    rope2_kernel<<<gr, 128, 0, s1>>>(qp, kp);

    // ---- attention split by batch halves; overlap Wo1-half0 with attn-half1 (R14 schedule) ----
    dim3 ga(14, 64);
    attn_kernel<<<ga, ATH, ATTN_SMEM, s1>>>(qp, kp, vp, aop, 0);
    cudaEventRecord(ev[3], s1);
    attn_kernel<<<ga, ATH, ATTN_SMEM, s1>>>(qp, kp, vp, aop, 64);
    cudaEventRecord(ev[4], s1);

    // s2: Wo1 batches 0-7
    cudaStreamWaitEvent(s2, ev[3], 0);
    dim3 go1h(16, M1h / 128);
    hgemm_kernel<<<go1h, 256, G_SMEM, s2>>>(aop, HDc, Wo1T, HDc, outp, outp, outp, D1c,
                                            M1h, HDc, L1c, Nc, 0, M1h, 0, 0, 16, 0);
    // s2: Wo2
    cudaStreamWaitEvent(s2, ev[4], 0);
    dim3 go2(8, (M2 + 127) / 128);
    hgemm_kernel<<<go2, 256, G_SMEM, s2>>>(aop, HDc, Wo2T, HDc,
                                           outp + (size_t)Bc * L1c * D1c,
                                           outp + (size_t)Bc * L1c * D1c,
                                           outp + (size_t)Bc * L1c * D1c, D2c,
                                           M2, HDc, L2c, Nc, L1c, M2, 0, 0, 8, 0);

    // s1: Wo1 batches 8-15
    hgemm_kernel<<<go1h, 256, G_SMEM, s1>>>(aop, HDc, Wo1T, HDc, outp, outp, outp, D1c,
                                            M1h, HDc, L1c, Nc, 8 * Nc, M1h, 0, 8 * L1c, 16, 0);

    // ---- join ----
    cudaEventRecord(ev[5], s2);
    cudaStreamWaitEvent(s1, ev[5], 0);
}

// round 17
// speedup vs baseline: 1.5736x; 1.0055x over previous
#include <cuda_runtime.h>
#include <cuda_fp16.h>
#include <math.h>
#include <stdint.h>

// Problem constants
#define Bc   16
#define L1c  816
#define L2c  51
#define Nc   867
#define Hc   8
#define DHc  256
#define D1c  2048
#define D2c  1024
#define HDc  2048

// ---------------- Scratch (half precision pipeline) ----------------
__device__ __half g_h1h[(size_t)Bc * L1c * D1c];
__device__ __half g_h2h[(size_t)Bc * L2c * D2c];
__device__ __half g_qh [(size_t)Bc * Nc  * HDc];
__device__ __half g_kh [(size_t)Bc * Nc  * HDc];
__device__ __half g_vh [(size_t)Bc * Nc  * HDc];
__device__ __half g_aoh[(size_t)Bc * Nc  * HDc];
__device__ __half g_wth[(size_t)6144*2048 + 6144*1024 + 2048*2048 + 1024*2048];

__device__ __forceinline__ uint32_t smem_u32(const void* p) {
    uint32_t a;
    asm("{ .reg .u64 t; cvta.to.shared.u64 t, %1; cvt.u32.u64 %0, t; }" : "=r"(a) : "l"(p));
    return a;
}
__device__ __forceinline__ void cp16(uint32_t dst, const void* src, bool pred) {
    int sz = pred ? 16 : 0;
    asm volatile("cp.async.cg.shared.global [%0], [%1], 16, %2;"
                 :: "r"(dst), "l"(src), "r"(sz) : "memory");
}
__device__ __forceinline__ void cp_commit() {
    asm volatile("cp.async.commit_group;" ::: "memory");
}
__device__ __forceinline__ void ldm4(unsigned* a, uint32_t addr) {
    asm volatile("ldmatrix.sync.aligned.m8n8.x4.shared.b16 {%0,%1,%2,%3}, [%4];"
                 : "=r"(a[0]), "=r"(a[1]), "=r"(a[2]), "=r"(a[3]) : "r"(addr));
}
__device__ __forceinline__ void ldm4t(unsigned* a, uint32_t addr) {
    asm volatile("ldmatrix.sync.aligned.m8n8.x4.trans.shared.b16 {%0,%1,%2,%3}, [%4];"
                 : "=r"(a[0]), "=r"(a[1]), "=r"(a[2]), "=r"(a[3]) : "r"(addr));
}
#define HMMA(acc, a0,a1,a2,a3, b0,b1) \
    asm volatile( \
        "mma.sync.aligned.m16n8k16.row.col.f32.f16.f16.f32 " \
        "{%0,%1,%2,%3}, {%4,%5,%6,%7}, {%8,%9}, {%0,%1,%2,%3};" \
        : "+f"((acc)[0]), "+f"((acc)[1]), "+f"((acc)[2]), "+f"((acc)[3]) \
        : "r"(a0), "r"(a1), "r"(a2), "r"(a3), "r"(b0), "r"(b1))

__device__ __forceinline__ unsigned h2u(float lo, float hi) {
    __half2 h = __floats2half2_rn(lo, hi);
    return *(unsigned*)&h;
}

// ---------------- Round + transpose to half: out[n][k] = h(in[k][n]) ----------------
__global__ void transround_kernel(const float* __restrict__ in, __half* __restrict__ out,
                                  int K, int N) {
    __shared__ float tile[32][33];
    int nb = blockIdx.x * 32, kb = blockIdx.y * 32;
    int tx = threadIdx.x, ty = threadIdx.y;
    #pragma unroll
    for (int j = 0; j < 4; j++)
        tile[ty + j * 8][tx] = in[(size_t)(kb + ty + j * 8) * N + nb + tx];
    __syncthreads();
    #pragma unroll
    for (int j = 0; j < 4; j++)
        out[(size_t)(nb + ty + j * 8) * K + kb + tx] = __float2half_rn(tile[tx][ty + j * 8]);
}

__global__ void qkv_transround_kernel(const float* __restrict__ wq,
                                      const float* __restrict__ wk,
                                      const float* __restrict__ wv,
                                      __half* __restrict__ out, int K, int N) {
    __shared__ float tile[32][33];
    const float* in = (blockIdx.z == 0) ? wq : ((blockIdx.z == 1) ? wk : wv);
    __half* dst = out + (size_t)blockIdx.z * N * K;
    int nb = blockIdx.x * 32, kb = blockIdx.y * 32;
    int tx = threadIdx.x, ty = threadIdx.y;
    #pragma unroll
    for (int j = 0; j < 4; j++)
        tile[ty + j * 8][tx] = in[(size_t)(kb + ty + j * 8) * N + nb + tx];
    __syncthreads();
    #pragma unroll
    for (int j = 0; j < 4; j++)
        dst[(size_t)(nb + ty + j * 8) * K + kb + tx] = __float2half_rn(tile[tx][ty + j * 8]);
}

// ---------------- RMSNorm (writes half) ----------------
__global__ void rmsnorm_kernel(const float* __restrict__ x, const float* __restrict__ w,
                               __half* __restrict__ out, int D) {
    int row = blockIdx.x;
    const float* xr = x + (size_t)row * D;
    __half* orow = out + (size_t)row * D;
    float ss = 0.f;
    for (int d = threadIdx.x; d < D; d += blockDim.x) {
        float v = xr[d];
        ss += v * v;
    }
    __shared__ float red[256];
    red[threadIdx.x] = ss;
    __syncthreads();
    for (int s = 128; s > 0; s >>= 1) {
        if (threadIdx.x < s) red[threadIdx.x] += red[threadIdx.x + s];
        __syncthreads();
    }
    float scale = rsqrtf(red[0] / (float)D + 1e-6f);
    for (int d = threadIdx.x; d < D; d += blockDim.x)
        orow[d] = __float2half_rn(xr[d] * scale * (1.0f + w[d]));
}

// ---------------- FP16 GEMM (identical to R14/R16) ----------------
#define GBK 64
#define PH  72
#define A_STGH (128 * PH)
#define STG_H  (2 * A_STGH)
#define G_SMEM (3 * STG_H * 2)

__global__ __launch_bounds__(256, 2) void hgemm_kernel(
    const __half* __restrict__ A, int lda,
    const __half* __restrict__ Bt, int ldb,
    void* C0v, void* C1v, void* C2v, int ldc,
    int M, int K,
    int a_seg, int a_outer, int a_off,
    int c_seg, int c_outer, int c_off,
    int blocks_per_out, int half_out)
{
    extern __shared__ __half smh[];
    const int tid  = threadIdx.x;
    const int lane = tid & 31;
    const int warp = tid >> 5;
    const int wm   = warp >> 1;
    const int wn   = warp & 1;
    const int gg   = lane >> 2;
    const int t    = lane & 3;

    const int out = blockIdx.x / blocks_per_out;
    void* Cv = (out == 0) ? C0v : ((out == 1) ? C1v : C2v);
    const int colC = (blockIdx.x % blocks_per_out) * 128;
    const int rowBase = blockIdx.y * 128;
    const int niter = K / GBK;

    const int kc = (tid & 7) * 8;
    long aoffs[4];
    bool aval[4];
    #pragma unroll
    for (int j = 0; j < 4; j++) {
        int r = rowBase + (tid >> 3) + j * 32;
        aval[j] = r < M;
        aoffs[j] = aval[j] ? ((long)(r / a_seg) * a_outer + a_off + (r % a_seg)) * (long)lda : 0;
    }
    const __half* bgp = Bt + (size_t)(blockIdx.x * 128 + (tid >> 3)) * ldb + kc;

    const uint32_t ua = smem_u32(smh);
    uint32_t s_dst[4];
    #pragma unroll
    for (int j = 0; j < 4; j++)
        s_dst[j] = (uint32_t)(((((tid >> 3) + j * 32) * PH + kc)) * 2);

    const int lmoff = ((lane & 7) + ((lane >> 3) & 1) * 8) * PH + ((lane >> 4) & 1) * 8;

    uint32_t abase[3], bbase[3];
    #pragma unroll
    for (int s = 0; s < 3; s++) {
        abase[s] = ua + (uint32_t)(s * STG_H * 2) + (uint32_t)((wm * 32 * PH + lmoff) * 2);
        bbase[s] = ua + (uint32_t)(s * STG_H * 2) + (uint32_t)(A_STGH * 2)
                 + (uint32_t)((wn * 64 * PH + lmoff) * 2);
    }

    float acc[2][8][4];
    #pragma unroll
    for (int mt = 0; mt < 2; mt++)
        #pragma unroll
        for (int nt = 0; nt < 8; nt++)
            #pragma unroll
            for (int i = 0; i < 4; i++) acc[mt][nt][i] = 0.f;

    #pragma unroll
    for (int s = 0; s < 2; s++) {
        uint32_t sb_ = ua + (uint32_t)(s * STG_H * 2);
        int k0 = s * GBK;
        #pragma unroll
        for (int j = 0; j < 4; j++)
            cp16(sb_ + s_dst[j], A + aoffs[j] + k0 + kc, aval[j]);
        #pragma unroll
        for (int j = 0; j < 4; j++)
            cp16(sb_ + (uint32_t)(A_STGH * 2) + s_dst[j], bgp + (size_t)j * 32 * ldb + k0, true);
        cp_commit();
    }

    int buf = 0, wbuf = 2;
    for (int it = 0; it < niter; it++) {
        asm volatile("cp.async.wait_group 1;" ::: "memory");
        __syncthreads();
        if (it + 2 < niter) {
            uint32_t sb_ = ua + (uint32_t)(wbuf * STG_H * 2);
            int k0 = (it + 2) * GBK;
            #pragma unroll
            for (int j = 0; j < 4; j++)
                cp16(sb_ + s_dst[j], A + aoffs[j] + k0 + kc, aval[j]);
            #pragma unroll
            for (int j = 0; j < 4; j++)
                cp16(sb_ + (uint32_t)(A_STGH * 2) + s_dst[j], bgp + (size_t)j * 32 * ldb + k0, true);
        }
        cp_commit();

        const uint32_t ab = abase[buf];
        const uint32_t bb = bbase[buf];
        #pragma unroll
        for (int ks = 0; ks < 4; ks++) {
            unsigned afr[2][4];
            ldm4(afr[0], ab + (uint32_t)(ks * 16 * 2));
            ldm4(afr[1], ab + (uint32_t)((16 * PH + ks * 16) * 2));
            unsigned br[4][4];
            #pragma unroll
            for (int p = 0; p < 4; p++)
                ldm4(br[p], bb + (uint32_t)((p * 16 * PH + ks * 16) * 2));
            #pragma unroll
            for (int mt = 0; mt < 2; mt++)
                #pragma unroll
                for (int p = 0; p < 4; p++) {
                    HMMA(acc[mt][2*p],   afr[mt][0], afr[mt][1], afr[mt][2], afr[mt][3],
                         br[p][0], br[p][2]);
                    HMMA(acc[mt][2*p+1], afr[mt][0], afr[mt][1], afr[mt][2], afr[mt][3],
                         br[p][1], br[p][3]);
                }
        }
        buf  = (buf  == 2) ? 0 : buf + 1;
        wbuf = (wbuf == 2) ? 0 : wbuf + 1;
    }

    #pragma unroll
    for (int mt = 0; mt < 2; mt++) {
        #pragma unroll
        for (int half = 0; half < 2; half++) {
            int r = rowBase + wm * 32 + mt * 16 + gg + half * 8;
            if (r >= M) continue;
            long crow = (long)(r / c_seg) * c_outer + c_off + (r % c_seg);
            if (half_out) {
                __half* cp = (__half*)Cv + crow * ldc + colC + wn * 64 + 2 * t;
                #pragma unroll
                for (int nt = 0; nt < 8; nt++) {
                    __half2 v = __floats2half2_rn(acc[mt][nt][half * 2], acc[mt][nt][half * 2 + 1]);
                    *(__half2*)(cp + nt * 8) = v;
                }
            } else {
                float* cp = (float*)Cv + crow * ldc + colC + wn * 64 + 2 * t;
                #pragma unroll
                for (int nt = 0; nt < 8; nt++)
                    *(float2*)(cp + nt * 8) = make_float2(acc[mt][nt][half * 2],
                                                          acc[mt][nt][half * 2 + 1]);
            }
        }
    }
}

// ---------------- RoPE on K only (q-rope fused into attention) ----------------
__global__ void ropek_kernel(__half* __restrict__ k) {
    int bn = blockIdx.x;
    int n  = bn % Nc;
    int i  = threadIdx.x;   // 0..127
    float inv_ts = exp2f(-13.287712379549449f * ((float)i * (1.0f / 128.0f)));
    float rad = (float)n * inv_ts;
    float s, c;
    sincosf(rad, &s, &c);
    #pragma unroll
    for (int h = 0; h < Hc; h++) {
        __half* pk = k + ((size_t)bn * Hc + h) * DHc;
        float ka = __half2float(pk[i]), kb2 = __half2float(pk[i + 128]);
        pk[i]       = __float2half_rn(ka * c - kb2 * s);
        pk[i + 128] = __float2half_rn(kb2 * c + ka * s);
    }
}

// ---------------- FP16 flash attention: q-rope fused into Q tile ----------------
#define AQT 64
#define AKT 32
#define PA  264
#define ATH 128
#define KVSTR (2 * AKT * PA)
#define ATTN_SMEM ((AQT + 4 * AKT) * PA * 2)

__device__ __forceinline__ int row_kmax(int qi) {
    if (qi >= Nc) return 0;
    return (qi < L1c) ? L1c : ((qi == L1c) ? (L1c + 1) : Nc);
}

__global__ __launch_bounds__(ATH, 2) void attn_kernel(
    const __half* __restrict__ q, const __half* __restrict__ k,
    const __half* __restrict__ v, __half* __restrict__ o, int bh_base)
{
    extern __shared__ __half smh[];
    __half* Qs = smh;
    __half* KV = Qs + AQT * PA;

    const int bh = bh_base + blockIdx.y;
    const int b = bh >> 3, h = bh & 7;
    const int qBase = blockIdx.x * AQT;
    const int tid = threadIdx.x;
    const int lane = tid & 31, warp = tid >> 5;
    const int g = lane >> 2, t = lane & 3;
    const size_t bhoff = (size_t)b * Nc * HDc + (size_t)h * DHc;

    const uint32_t uq  = smem_u32(Qs);
    const uint32_t ukv = smem_u32(KV);

    // Q tile: raw (un-roped, unscaled) q
    #pragma unroll
    for (int j = 0; j < 16; j++) {
        int i = tid + j * ATH;
        int r = i >> 5, c8 = (i & 31) * 8;
        int qi = qBase + r;
        cp16(uq + (uint32_t)((r * PA + c8) * 2), q + bhoff + (size_t)qi * HDc + c8, qi < Nc);
    }
    cp_commit();

    const int qrow = warp * 16;
    const int qi0 = qBase + qrow + g;
    const int qi1 = qi0 + 8;
    const int kmax0 = row_kmax(qi0);
    const int kmax1 = row_kmax(qi1);

    float m0 = -1e30f, m1 = -1e30f, l0 = 0.f, l1 = 0.f;
    float acc[32][4];
    #pragma unroll
    for (int nt = 0; nt < 32; nt++)
        #pragma unroll
        for (int i = 0; i < 4; i++) acc[nt][i] = 0.f;

    const int qlast = min(qBase + AQT - 1, Nc - 1);
    const int kb = (qlast < L1c) ? L1c : ((qlast == L1c) ? (L1c + 1) : Nc);
    const int ntiles = (kb + AKT - 1) / AKT;

    const int lmoff = ((lane & 7) + ((lane >> 3) & 1) * 8) * PA + ((lane >> 4) & 1) * 8;
    const uint32_t qbase = uq + (uint32_t)((qrow * PA + lmoff) * 2);

    {
        uint32_t dst = ukv;
        #pragma unroll
        for (int j = 0; j < 8; j++) {
            int i = tid + j * ATH;
            int r = i >> 5, c8 = (i & 31) * 8;
            bool pv = r < Nc;
            cp16(dst + (uint32_t)((r * PA + c8) * 2), k + bhoff + (size_t)r * HDc + c8, pv);
            cp16(dst + (uint32_t)(((AKT + r) * PA + c8) * 2), v + bhoff + (size_t)r * HDc + c8, pv);
        }
        cp_commit();
    }

    for (int it = 0; it < ntiles; it++) {
        if (it + 1 < ntiles) {
            uint32_t dst = ukv + (uint32_t)(((it + 1) & 1) * KVSTR * 2);
            int k0n = (it + 1) * AKT;
            #pragma unroll
            for (int j = 0; j < 8; j++) {
                int i = tid + j * ATH;
                int r = i >> 5, c8 = (i & 31) * 8;
                int ki = k0n + r;
                bool pv = ki < Nc;
                cp16(dst + (uint32_t)((r * PA + c8) * 2), k + bhoff + (size_t)ki * HDc + c8, pv);
                cp16(dst + (uint32_t)(((AKT + r) * PA + c8) * 2), v + bhoff + (size_t)ki * HDc + c8, pv);
            }
        }
        cp_commit();
        asm volatile("cp.async.wait_group 1;" ::: "memory");
        __syncthreads();

        // ---- fused q-rope (+1/16 fold + fp16 round) on the Q smem tile, once ----
        if (it == 0) {
            for (int idx = tid; idx < AQT * 128; idx += ATH) {
                int r = idx >> 7, i = idx & 127;
                int qi = qBase + r;
                if (qi < Nc) {
                    float inv_ts = exp2f(-13.287712379549449f * ((float)i * (1.0f / 128.0f)));
                    float rad = (float)qi * inv_ts;
                    float s, c;
                    sincosf(rad, &s, &c);
                    float xa = __half2float(Qs[r * PA + i]);
                    float xb = __half2float(Qs[r * PA + i + 128]);
                    Qs[r * PA + i]       = __float2half_rn((xa * c - xb * s) * 0.0625f);
                    Qs[r * PA + i + 128] = __float2half_rn((xb * c + xa * s) * 0.0625f);
                }
            }
            __syncthreads();
        }

        const int k0 = it * AKT;
        const uint32_t kbase = ukv + (uint32_t)((it & 1) * KVSTR * 2) + (uint32_t)(lmoff * 2);
        const uint32_t vbase = kbase + (uint32_t)(AKT * PA * 2);

        float sc[4][4];
        #pragma unroll
        for (int nt = 0; nt < 4; nt++)
            #pragma unroll
            for (int i = 0; i < 4; i++) sc[nt][i] = 0.f;

        #pragma unroll
        for (int ks = 0; ks < 16; ks++) {
            unsigned aq[4];
            ldm4(aq, qbase + (uint32_t)(ks * 16 * 2));
            unsigned bk[2][4];
            ldm4(bk[0], kbase + (uint32_t)((ks * 16) * 2));
            ldm4(bk[1], kbase + (uint32_t)((16 * PA + ks * 16) * 2));
            #pragma unroll
            for (int p = 0; p < 2; p++) {
                HMMA(sc[2*p],   aq[0], aq[1], aq[2], aq[3], bk[p][0], bk[p][2]);
                HMMA(sc[2*p+1], aq[0], aq[1], aq[2], aq[3], bk[p][1], bk[p][3]);
            }
        }

        #pragma unroll
        for (int nt = 0; nt < 4; nt++) {
            int key = k0 + nt * 8 + 2 * t;
            if (key     >= kmax0) sc[nt][0] = -1e30f;
            if (key + 1 >= kmax0) sc[nt][1] = -1e30f;
            if (key     >= kmax1) sc[nt][2] = -1e30f;
            if (key + 1 >= kmax1) sc[nt][3] = -1e30f;
        }
        float rmax0 = -1e30f, rmax1 = -1e30f;
        #pragma unroll
        for (int nt = 0; nt < 4; nt++) {
            rmax0 = fmaxf(rmax0, fmaxf(sc[nt][0], sc[nt][1]));
            rmax1 = fmaxf(rmax1, fmaxf(sc[nt][2], sc[nt][3]));
        }
        #pragma unroll
        for (int off = 1; off <= 2; off <<= 1) {
            rmax0 = fmaxf(rmax0, __shfl_xor_sync(0xffffffffu, rmax0, off));
            rmax1 = fmaxf(rmax1, __shfl_xor_sync(0xffffffffu, rmax1, off));
        }
        float nm0 = fmaxf(m0, rmax0), nm1 = fmaxf(m1, rmax1);
        float corr0 = __expf(m0 - nm0), corr1 = __expf(m1 - nm1);
        m0 = nm0; m1 = nm1;

        float pr[4][4];
        float psum0 = 0.f, psum1 = 0.f;
        #pragma unroll
        for (int nt = 0; nt < 4; nt++) {
            pr[nt][0] = __expf(sc[nt][0] - nm0);
            pr[nt][1] = __expf(sc[nt][1] - nm0);
            pr[nt][2] = __expf(sc[nt][2] - nm1);
            pr[nt][3] = __expf(sc[nt][3] - nm1);
            psum0 += pr[nt][0] + pr[nt][1];
            psum1 += pr[nt][2] + pr[nt][3];
        }
        l0 = l0 * corr0 + psum0;
        l1 = l1 * corr1 + psum1;
        #pragma unroll
        for (int nt = 0; nt < 32; nt++) {
            acc[nt][0] *= corr0; acc[nt][1] *= corr0;
            acc[nt][2] *= corr1; acc[nt][3] *= corr1;
        }

        #pragma unroll
        for (int kc2 = 0; kc2 < 2; kc2++) {
            unsigned pa0 = h2u(pr[2*kc2][0],   pr[2*kc2][1]);
            unsigned pa1 = h2u(pr[2*kc2][2],   pr[2*kc2][3]);
            unsigned pa2 = h2u(pr[2*kc2+1][0], pr[2*kc2+1][1]);
            unsigned pa3 = h2u(pr[2*kc2+1][2], pr[2*kc2+1][3]);
            #pragma unroll
            for (int nt2 = 0; nt2 < 16; nt2++) {
                unsigned bv[4];
                ldm4t(bv, vbase + (uint32_t)((kc2 * 16 * PA + nt2 * 16) * 2));
                HMMA(acc[2*nt2],   pa0, pa1, pa2, pa3, bv[0], bv[1]);
                HMMA(acc[2*nt2+1], pa0, pa1, pa2, pa3, bv[2], bv[3]);
            }
        }
        __syncthreads();
    }

    l0 += __shfl_xor_sync(0xffffffffu, l0, 1);
    l0 += __shfl_xor_sync(0xffffffffu, l0, 2);
    l1 += __shfl_xor_sync(0xffffffffu, l1, 1);
    l1 += __shfl_xor_sync(0xffffffffu, l1, 2);

    float inv0 = 1.0f / l0, inv1 = 1.0f / l1;
    if (qi0 < Nc) {
        __half* op = o + bhoff + (size_t)qi0 * HDc + 2 * t;
        #pragma unroll
        for (int nt = 0; nt < 32; nt++)
            *(__half2*)(op + nt * 8) = __floats2half2_rn(acc[nt][0] * inv0, acc[nt][1] * inv0);
    }
    if (qi1 < Nc) {
        __half* op = o + bhoff + (size_t)qi1 * HDc + 2 * t;
        #pragma unroll
        for (int nt = 0; nt < 32; nt++)
            *(__half2*)(op + nt * 8) = __floats2half2_rn(acc[nt][2] * inv1, acc[nt][3] * inv1);
    }
}

// ---------------- Host launch ----------------
extern "C" void kernel_launch(void* const* d_in, const int* in_sizes, int n_in,
                              void* d_out, int out_size) {
    const float* x1   = (const float*)d_in[0];
    const float* x2   = (const float*)d_in[1];
    const float* ln1w = (const float*)d_in[2];
    const float* ln2w = (const float*)d_in[3];
    const float* Wq1  = (const float*)d_in[4];
    const float* Wk1  = (const float*)d_in[5];
    const float* Wv1  = (const float*)d_in[6];
    const float* Wo1  = (const float*)d_in[7];
    const float* Wq2  = (const float*)d_in[8];
    const float* Wk2  = (const float*)d_in[9];
    const float* Wv2  = (const float*)d_in[10];
    const float* Wo2  = (const float*)d_in[11];

    static __half *h1p = nullptr, *h2p = nullptr, *qp = nullptr, *kp = nullptr,
                  *vp = nullptr, *aop = nullptr, *wtp = nullptr;
    static cudaStream_t s2 = nullptr, s3 = nullptr;
    static cudaEvent_t ev[8];
    static bool inited = false;
    if (!inited) {
        cudaGetSymbolAddress((void**)&h1p, g_h1h);
        cudaGetSymbolAddress((void**)&h2p, g_h2h);
        cudaGetSymbolAddress((void**)&qp,  g_qh);
        cudaGetSymbolAddress((void**)&kp,  g_kh);
        cudaGetSymbolAddress((void**)&vp,  g_vh);
        cudaGetSymbolAddress((void**)&aop, g_aoh);
        cudaGetSymbolAddress((void**)&wtp, g_wth);
        cudaStreamCreateWithFlags(&s2, cudaStreamNonBlocking);
        cudaStreamCreateWithFlags(&s3, cudaStreamNonBlocking);
        for (int i = 0; i < 8; i++)
            cudaEventCreateWithFlags(&ev[i], cudaEventDisableTiming);
        cudaFuncSetAttribute(attn_kernel,
                             cudaFuncAttributeMaxDynamicSharedMemorySize, ATTN_SMEM);
        cudaFuncSetAttribute(hgemm_kernel,
                             cudaFuncAttributeMaxDynamicSharedMemorySize, G_SMEM);
        inited = true;
    }

    float* outp = (float*)d_out;
    const int M1 = Bc * L1c;   // 13056
    const int M2 = Bc * L2c;   // 816
    const int M1h = M1 / 2;    // 6528

    __half* Wqkv1T = wtp;
    __half* Wqkv2T = Wqkv1T + (size_t)6144 * 2048;
    __half* Wo1T   = Wqkv2T + (size_t)6144 * 1024;
    __half* Wo2T   = Wo1T   + (size_t)2048 * 2048;

    dim3 tb(32, 8);
    cudaStream_t s1 = 0;

    // ---- fork: s2 (stream-2 pipeline), s3 (rmsnorm1) ----
    cudaEventRecord(ev[0], s1);
    cudaStreamWaitEvent(s2, ev[0], 0);
    cudaStreamWaitEvent(s3, ev[0], 0);

    // s3: rmsnorm1 concurrent with QKV1 weight transround
    rmsnorm_kernel<<<M1, 256, 0, s3>>>(x1, ln1w, h1p, D1c);
    cudaEventRecord(ev[1], s3);

    // s1: QKV1 weights, then QKV1 GEMM
    qkv_transround_kernel<<<dim3(HDc/32, D1c/32, 3), tb, 0, s1>>>(Wq1, Wk1, Wv1, Wqkv1T, D1c, HDc);
    cudaStreamWaitEvent(s1, ev[1], 0);
    dim3 gq1(48, M1 / 128);
    hgemm_kernel<<<gq1, 256, G_SMEM, s1>>>(h1p, D1c, Wqkv1T, D1c, qp, kp, vp, HDc,
                                           M1, D1c, M1, 0, 0, L1c, Nc, 0, 16, 1);

    // s2: stream-2 prep + QKV2, then Wo weights
    qkv_transround_kernel<<<dim3(HDc/32, D2c/32, 3), tb, 0, s2>>>(Wq2, Wk2, Wv2, Wqkv2T, D2c, HDc);
    rmsnorm_kernel<<<M2, 256, 0, s2>>>(x2, ln2w, h2p, D2c);
    dim3 gq2(48, (M2 + 127) / 128);
    hgemm_kernel<<<gq2, 256, G_SMEM, s2>>>(h2p, D2c, Wqkv2T, D2c, qp, kp, vp, HDc,
                                           M2, D2c, M2, 0, 0, L2c, Nc, L1c, 16, 1);
    cudaEventRecord(ev[2], s2);
    transround_kernel<<<dim3(D1c/32, HDc/32), tb, 0, s2>>>(Wo1, Wo1T, HDc, D1c);
    transround_kernel<<<dim3(D2c/32, HDc/32), tb, 0, s2>>>(Wo2, Wo2T, HDc, D2c);

    // ---- rope on K only (q-rope fused into attention) ----
    cudaStreamWaitEvent(s1, ev[2], 0);
    ropek_kernel<<<Bc * Nc, 128, 0, s1>>>(kp);

    // ---- attention split by batch halves; overlap Wo1-half0 with attn-half1 ----
    dim3 ga(14, 64);
    attn_kernel<<<ga, ATH, ATTN_SMEM, s1>>>(qp, kp, vp, aop, 0);
    cudaEventRecord(ev[3], s1);
    attn_kernel<<<ga, ATH, ATTN_SMEM, s1>>>(qp, kp, vp, aop, 64);
    cudaEventRecord(ev[4], s1);

    // s2: Wo1 batches 0-7
    cudaStreamWaitEvent(s2, ev[3], 0);
    dim3 go1h(16, M1h / 128);
    hgemm_kernel<<<go1h, 256, G_SMEM, s2>>>(aop, HDc, Wo1T, HDc, outp, outp, outp, D1c,
                                            M1h, HDc, L1c, Nc, 0, M1h, 0, 0, 16, 0);
    // s2: Wo2
    cudaStreamWaitEvent(s2, ev[4], 0);
    dim3 go2(8, (M2 + 127) / 128);
    hgemm_kernel<<<go2, 256, G_SMEM, s2>>>(aop, HDc, Wo2T, HDc,
                                           outp + (size_t)Bc * L1c * D1c,
                                           outp + (size_t)Bc * L1c * D1c,
                                           outp + (size_t)Bc * L1c * D1c, D2c,
                                           M2, HDc, L2c, Nc, L1c, M2, 0, 0, 8, 0);

    // s1: Wo1 batches 8-15
    hgemm_kernel<<<go1h, 256, G_SMEM, s1>>>(aop, HDc, Wo1T, HDc, outp, outp, outp, D1c,
                                            M1h, HDc, L1c, Nc, 8 * Nc, M1h, 0, 8 * L1c, 16, 0);

    // ---- join ----
    cudaEventRecord(ev[5], s2);
    cudaStreamWaitEvent(s1, ev[5], 0);
}